// round 10
// baseline (speedup 1.0000x reference)
#include <cuda_runtime.h>
#include <cuda_bf16.h>

// binary contrastive loss, single fused persistent kernel:
//   sim0[i] = <x[i],x[i]>/temp ; sim1[i] = <x[i],x[samples[i]]>/temp
//   out = mean_i -log(sigmoid(diff)+eps)*label - log(1-sigmoid+eps)*(1-label)
//
// x: [16384, 2048] fp32 ; y, samples: int32 ; out: 1 fp32.
//
// Lessons: R3 no fences; R4 block-per-row; R6 persistent 1184x256 tiny smem;
// R7 big-smem kills occupancy; R8 split L2 policy (gather=evict_last) 25.3us;
// R9 all-evict_last thrashes (29.2us).
// This round: keep xj gathers evict_last (pins ~81MB of sampled rows in L2),
// but make the xi sweep PLAIN loads (evict_normal). R8 used evict_first on
// the sweep, which demotes pinned lines on hit -> the sweep un-pinned the
// gather set and missed rows that were resident. Plain loads hit the pinned
// set (~63% of rows are sampled) without demoting it. Also prefetch next
// iteration's samples[] to take the scalar load off the address chain.

#define TEMP_INV 10.0f
#define EPS 1e-5f
#define MAX_ITERS 16
#define GRID_BLOCKS (148 * 8)

__device__ float        g_accum;    // zero at module load; winner resets
__device__ unsigned int g_ticket;   // monotonic; used mod gridDim.x

__device__ __forceinline__ float4 ld_f4_policy(const float4* p, unsigned long long pol) {
    float4 v;
    asm volatile("ld.global.L2::cache_hint.v4.f32 {%0,%1,%2,%3}, [%4], %5;"
                 : "=f"(v.x), "=f"(v.y), "=f"(v.z), "=f"(v.w)
                 : "l"(p), "l"(pol));
    return v;
}

__global__ __launch_bounds__(256, 8) void fused_loss_kernel(
    const float* __restrict__ x,
    const int* __restrict__ y,
    const int* __restrict__ samples,
    float* __restrict__ out,
    int B, int D, float invB)
{
    __shared__ float sh0[MAX_ITERS][8];
    __shared__ float sh1[MAX_ITERS][8];

    const int tid  = threadIdx.x;
    const int w    = tid >> 5;
    const int lane = tid & 31;
    const int t0   = tid;
    const int t1   = tid + 256;

    unsigned long long pol_keep;
    asm volatile("createpolicy.fractional.L2::evict_last.b64 %0, 1.0;" : "=l"(pol_keep));

    int i    = blockIdx.x;
    int j    = (i < B) ? samples[i] : 0;
    int iter = 0;

    for (; i < B; iter++) {
        const float4* xi = reinterpret_cast<const float4*>(x + (size_t)i * D);
        const float4* xj = reinterpret_cast<const float4*>(x + (size_t)j * D);

        // front-batch all 4 row loads:
        //   xi sweep: PLAIN loads (evict_normal) -> hit pinned rows, no demote
        //   xj gather: evict_last -> pin the sampled working set in L2
        float4 a0 = xi[t0];
        float4 a1 = xi[t1];
        float4 b0 = ld_f4_policy(xj + t0, pol_keep);
        float4 b1 = ld_f4_policy(xj + t1, pol_keep);

        // prefetch next iteration's sample index off the critical path
        const int i_next = i + gridDim.x;
        const int j_next = (i_next < B) ? samples[i_next] : 0;

        float s0, s1;
        s0 = a0.x * a0.x;            s1 = a0.x * b0.x;
        s0 = fmaf(a0.y, a0.y, s0);   s1 = fmaf(a0.y, b0.y, s1);
        s0 = fmaf(a0.z, a0.z, s0);   s1 = fmaf(a0.z, b0.z, s1);
        s0 = fmaf(a0.w, a0.w, s0);   s1 = fmaf(a0.w, b0.w, s1);
        s0 = fmaf(a1.x, a1.x, s0);   s1 = fmaf(a1.x, b1.x, s1);
        s0 = fmaf(a1.y, a1.y, s0);   s1 = fmaf(a1.y, b1.y, s1);
        s0 = fmaf(a1.z, a1.z, s0);   s1 = fmaf(a1.z, b1.z, s1);
        s0 = fmaf(a1.w, a1.w, s0);   s1 = fmaf(a1.w, b1.w, s1);

        #pragma unroll
        for (int o = 16; o > 0; o >>= 1) {
            s0 += __shfl_xor_sync(0xFFFFFFFFu, s0, o);
            s1 += __shfl_xor_sync(0xFFFFFFFFu, s1, o);
        }

        if (lane == 0) { sh0[iter][w] = s0; sh1[iter][w] = s1; }

        i = i_next;
        j = j_next;
    }
    const int niter = iter;            // <= 14
    __syncthreads();                   // the ONLY sync

    // parallel epilogue: thread t handles row t of this block
    float loss = 0.0f;
    if (tid < niter) {
        const int ri = blockIdx.x + tid * gridDim.x;
        const int rj = samples[ri];

        float r0 = sh0[tid][0], r1 = sh1[tid][0];
        #pragma unroll
        for (int k = 1; k < 8; k++) { r0 += sh0[tid][k]; r1 += sh1[tid][k]; }

        const float diff  = (r0 - r1) * TEMP_INV;
        const float p     = 1.0f / (1.0f + expf(-diff));
        const float label = (y[ri] != y[rj]) ? 1.0f : 0.0f;
        loss = -logf(p + EPS) * label
               - logf(1.0f - p + EPS) * (1.0f - label);
    }

    // niter <= 16 < 32 -> only warp 0 holds nonzero losses
    if (w == 0) {
        #pragma unroll
        for (int o = 16; o > 0; o >>= 1)
            loss += __shfl_xor_sync(0xFFFFFFFFu, loss, o);

        if (lane == 0) {
            atomicAdd(&g_accum, loss);             // relaxed, performed at L2

            unsigned int t;
            asm volatile("atom.add.acq_rel.gpu.global.u32 %0, [%1], 1;"
                         : "=r"(t) : "l"(&g_ticket) : "memory");

            if (t % gridDim.x == gridDim.x - 1) {  // last block to arrive
                const float total = atomicAdd(&g_accum, 0.0f);
                out[0] = total * invB;
                atomicExch(&g_accum, 0.0f);        // reset for next replay
            }
        }
    }
}

extern "C" void kernel_launch(void* const* d_in, const int* in_sizes, int n_in,
                              void* d_out, int out_size)
{
    const float* x       = (const float*)d_in[0];
    const int*   y       = (const int*)d_in[1];
    const int*   samples = (const int*)d_in[2];
    float* out = (float*)d_out;

    const int B = in_sizes[1];                 // 16384
    const int D = in_sizes[0] / in_sizes[1];   // 2048

    int blocks = GRID_BLOCKS;                  // 1184 persistent blocks
    if (blocks > B) blocks = B;

    fused_loss_kernel<<<blocks, 256>>>(x, y, samples, out, B, D, 1.0f / (float)B);
}

// round 11
// speedup vs baseline: 1.2121x; 1.2121x over previous
#include <cuda_runtime.h>
#include <cuda_bf16.h>

// binary contrastive loss, single fused persistent kernel:
//   sim0[i] = <x[i],x[i]>/temp ; sim1[i] = <x[i],x[samples[i]]>/temp
//   out = mean_i -log(sigmoid(diff)+eps)*label - log(1-sigmoid+eps)*(1-label)
//
// x: [16384, 2048] fp32 ; y, samples: int32 ; out: 1 fp32.
//
// Verified lessons: R3 no fences; R4 block-per-row; R6 persistent 1184x256
// tiny smem; R7 big smem kills occupancy; R8 split L2 policy WINS (25.3us):
//   sweep=evict_first (never pollutes L2), gather=evict_last (pins sampled
//   rows, ~81MB, across graph replays); R9 all-evict_last thrashes; R10
//   sweep=normal churns the pinned set. Warm state is ~90% of the LTS cap
//   (256MB logical / 25.3us = 10.1TB/s) -> L2-throughput-bound.
// This round: exact R8 + samples[] prefetch (next row's index loaded before
// the FMA/shuffle tail, removing a dependent scalar L2 access from each
// row-start critical path). regs stay at 32 -> 8 blocks/SM preserved.

#define TEMP_INV 10.0f
#define EPS 1e-5f
#define MAX_ITERS 16
#define GRID_BLOCKS (148 * 8)

__device__ float        g_accum;    // zero at module load; winner resets
__device__ unsigned int g_ticket;   // monotonic; used mod gridDim.x

__device__ __forceinline__ float4 ld_f4_policy(const float4* p, unsigned long long pol) {
    float4 v;
    asm volatile("ld.global.L2::cache_hint.v4.f32 {%0,%1,%2,%3}, [%4], %5;"
                 : "=f"(v.x), "=f"(v.y), "=f"(v.z), "=f"(v.w)
                 : "l"(p), "l"(pol));
    return v;
}

__global__ __launch_bounds__(256, 8) void fused_loss_kernel(
    const float* __restrict__ x,
    const int* __restrict__ y,
    const int* __restrict__ samples,
    float* __restrict__ out,
    int B, int D, float invB)
{
    __shared__ float sh0[MAX_ITERS][8];
    __shared__ float sh1[MAX_ITERS][8];

    const int tid  = threadIdx.x;
    const int w    = tid >> 5;
    const int lane = tid & 31;
    const int t0   = tid;
    const int t1   = tid + 256;

    unsigned long long pol_stream, pol_keep;
    asm volatile("createpolicy.fractional.L2::evict_first.b64 %0, 1.0;" : "=l"(pol_stream));
    asm volatile("createpolicy.fractional.L2::evict_last.b64  %0, 1.0;" : "=l"(pol_keep));

    int i    = blockIdx.x;
    int j    = (i < B) ? samples[i] : 0;
    int iter = 0;

    for (; i < B; iter++) {
        const float4* xi = reinterpret_cast<const float4*>(x + (size_t)i * D);
        const float4* xj = reinterpret_cast<const float4*>(x + (size_t)j * D);

        // front-batch all 4 loads; stream=evict_first, gather=evict_last
        float4 a0 = ld_f4_policy(xi + t0, pol_stream);
        float4 a1 = ld_f4_policy(xi + t1, pol_stream);
        float4 b0 = ld_f4_policy(xj + t0, pol_keep);
        float4 b1 = ld_f4_policy(xj + t1, pol_keep);

        // prefetch next row's sample index off the critical path
        const int i_next = i + gridDim.x;
        const int j_next = (i_next < B) ? samples[i_next] : 0;

        float s0, s1;
        s0 = a0.x * a0.x;            s1 = a0.x * b0.x;
        s0 = fmaf(a0.y, a0.y, s0);   s1 = fmaf(a0.y, b0.y, s1);
        s0 = fmaf(a0.z, a0.z, s0);   s1 = fmaf(a0.z, b0.z, s1);
        s0 = fmaf(a0.w, a0.w, s0);   s1 = fmaf(a0.w, b0.w, s1);
        s0 = fmaf(a1.x, a1.x, s0);   s1 = fmaf(a1.x, b1.x, s1);
        s0 = fmaf(a1.y, a1.y, s0);   s1 = fmaf(a1.y, b1.y, s1);
        s0 = fmaf(a1.z, a1.z, s0);   s1 = fmaf(a1.z, b1.z, s1);
        s0 = fmaf(a1.w, a1.w, s0);   s1 = fmaf(a1.w, b1.w, s1);

        #pragma unroll
        for (int o = 16; o > 0; o >>= 1) {
            s0 += __shfl_xor_sync(0xFFFFFFFFu, s0, o);
            s1 += __shfl_xor_sync(0xFFFFFFFFu, s1, o);
        }

        if (lane == 0) { sh0[iter][w] = s0; sh1[iter][w] = s1; }

        i = i_next;
        j = j_next;
    }
    const int niter = iter;            // <= 14
    __syncthreads();                   // the ONLY sync

    // parallel epilogue: thread t handles row t of this block
    float loss = 0.0f;
    if (tid < niter) {
        const int ri = blockIdx.x + tid * gridDim.x;
        const int rj = samples[ri];

        float r0 = sh0[tid][0], r1 = sh1[tid][0];
        #pragma unroll
        for (int k = 1; k < 8; k++) { r0 += sh0[tid][k]; r1 += sh1[tid][k]; }

        const float diff  = (r0 - r1) * TEMP_INV;
        const float p     = 1.0f / (1.0f + expf(-diff));
        const float label = (y[ri] != y[rj]) ? 1.0f : 0.0f;
        loss = -logf(p + EPS) * label
               - logf(1.0f - p + EPS) * (1.0f - label);
    }

    // niter <= 16 < 32 -> only warp 0 holds nonzero losses
    if (w == 0) {
        #pragma unroll
        for (int o = 16; o > 0; o >>= 1)
            loss += __shfl_xor_sync(0xFFFFFFFFu, loss, o);

        if (lane == 0) {
            atomicAdd(&g_accum, loss);             // relaxed, performed at L2

            unsigned int t;
            asm volatile("atom.add.acq_rel.gpu.global.u32 %0, [%1], 1;"
                         : "=r"(t) : "l"(&g_ticket) : "memory");

            if (t % gridDim.x == gridDim.x - 1) {  // last block to arrive
                const float total = atomicAdd(&g_accum, 0.0f);
                out[0] = total * invB;
                atomicExch(&g_accum, 0.0f);        // reset for next replay
            }
        }
    }
}

extern "C" void kernel_launch(void* const* d_in, const int* in_sizes, int n_in,
                              void* d_out, int out_size)
{
    const float* x       = (const float*)d_in[0];
    const int*   y       = (const int*)d_in[1];
    const int*   samples = (const int*)d_in[2];
    float* out = (float*)d_out;

    const int B = in_sizes[1];                 // 16384
    const int D = in_sizes[0] / in_sizes[1];   // 2048

    int blocks = GRID_BLOCKS;                  // 1184 persistent blocks
    if (blocks > B) blocks = B;

    fused_loss_kernel<<<blocks, 256>>>(x, y, samples, out, B, D, 1.0f / (float)B);
}

// round 12
// speedup vs baseline: 1.2183x; 1.0051x over previous
#include <cuda_runtime.h>
#include <cuda_bf16.h>

// binary contrastive loss, single fused persistent kernel:
//   sim0[i] = <x[i],x[i]>/temp ; sim1[i] = <x[i],x[samples[i]]>/temp
//   out = mean_i -log(sigmoid(diff)+eps)*label - log(1-sigmoid+eps)*(1-label)
//
// x: [16384, 2048] fp32 ; y, samples: int32 ; out: 1 fp32.
//
// Verified: R3 no fences; R4 block-per-row; R6 persistent 1184x256 tiny smem;
// R7 big smem kills occupancy; R8 split L2 policy = 25.3us (sweep=evict_first,
// gather=evict_last); R9/R10 other policy corners worse; R11 prefetch neutral.
// Warm state is ~92% of the LTS cap (256MB/25.3us = 10.6TB/s) -> L2-bound.
// This round: shrink the mainloop SHFL tail 10 -> 6 (butterfly o=16,8,4 only,
// 4 partials/warp stored as float2 to 3.6KB smem); finish the reduce in the
// epilogue. Cuts the largest non-LTS pipe load (MIO/SHFL) 40% per row with
// zero occupancy cost.

#define TEMP_INV 10.0f
#define EPS 1e-5f
#define MAX_ITERS 16
#define GRID_BLOCKS (148 * 8)

__device__ float        g_accum;    // zero at module load; winner resets
__device__ unsigned int g_ticket;   // monotonic; used mod gridDim.x

__device__ __forceinline__ float4 ld_f4_policy(const float4* p, unsigned long long pol) {
    float4 v;
    asm volatile("ld.global.L2::cache_hint.v4.f32 {%0,%1,%2,%3}, [%4], %5;"
                 : "=f"(v.x), "=f"(v.y), "=f"(v.z), "=f"(v.w)
                 : "l"(p), "l"(pol));
    return v;
}

__global__ __launch_bounds__(256, 8) void fused_loss_kernel(
    const float* __restrict__ x,
    const int* __restrict__ y,
    const int* __restrict__ samples,
    float* __restrict__ out,
    int B, int D, float invB)
{
    __shared__ float2 sh[MAX_ITERS][32];   // 8 warps x 4 partials per row, 4KB
    __shared__ float  shloss[MAX_ITERS];

    const int tid  = threadIdx.x;
    const int w    = tid >> 5;
    const int lane = tid & 31;
    const int t0   = tid;
    const int t1   = tid + 256;

    unsigned long long pol_stream, pol_keep;
    asm volatile("createpolicy.fractional.L2::evict_first.b64 %0, 1.0;" : "=l"(pol_stream));
    asm volatile("createpolicy.fractional.L2::evict_last.b64  %0, 1.0;" : "=l"(pol_keep));

    int i    = blockIdx.x;
    int j    = (i < B) ? samples[i] : 0;
    int iter = 0;

    for (; i < B; iter++) {
        const float4* xi = reinterpret_cast<const float4*>(x + (size_t)i * D);
        const float4* xj = reinterpret_cast<const float4*>(x + (size_t)j * D);

        // front-batch all 4 loads; stream=evict_first, gather=evict_last
        float4 a0 = ld_f4_policy(xi + t0, pol_stream);
        float4 a1 = ld_f4_policy(xi + t1, pol_stream);
        float4 b0 = ld_f4_policy(xj + t0, pol_keep);
        float4 b1 = ld_f4_policy(xj + t1, pol_keep);

        // prefetch next row's sample index off the critical path
        const int i_next = i + gridDim.x;
        const int j_next = (i_next < B) ? samples[i_next] : 0;

        float s0, s1;
        s0 = a0.x * a0.x;            s1 = a0.x * b0.x;
        s0 = fmaf(a0.y, a0.y, s0);   s1 = fmaf(a0.y, b0.y, s1);
        s0 = fmaf(a0.z, a0.z, s0);   s1 = fmaf(a0.z, b0.z, s1);
        s0 = fmaf(a0.w, a0.w, s0);   s1 = fmaf(a0.w, b0.w, s1);
        s0 = fmaf(a1.x, a1.x, s0);   s1 = fmaf(a1.x, b1.x, s1);
        s0 = fmaf(a1.y, a1.y, s0);   s1 = fmaf(a1.y, b1.y, s1);
        s0 = fmaf(a1.z, a1.z, s0);   s1 = fmaf(a1.z, b1.z, s1);
        s0 = fmaf(a1.w, a1.w, s0);   s1 = fmaf(a1.w, b1.w, s1);

        // partial butterfly: o=16,8,4 -> lane l holds sum over {l' : l'==l mod 4}
        #pragma unroll
        for (int o = 16; o >= 4; o >>= 1) {
            s0 += __shfl_xor_sync(0xFFFFFFFFu, s0, o);
            s1 += __shfl_xor_sync(0xFFFFFFFFu, s1, o);
        }

        if (lane < 4) sh[iter][(w << 2) + lane] = make_float2(s0, s1);

        i = i_next;
        j = j_next;
    }
    const int niter = iter;            // <= 14
    __syncthreads();                   // the ONLY sync before epilogue

    // epilogue: warp w finishes rows w and w+8 (32 partials each)
    #pragma unroll
    for (int pass = 0; pass < 2; pass++) {
        const int r = w + pass * 8;
        if (r < niter) {
            float2 v = sh[r][lane];
            float r0 = v.x, r1 = v.y;
            #pragma unroll
            for (int o = 16; o > 0; o >>= 1) {
                r0 += __shfl_xor_sync(0xFFFFFFFFu, r0, o);
                r1 += __shfl_xor_sync(0xFFFFFFFFu, r1, o);
            }
            if (lane == 0) {
                const int ri = blockIdx.x + r * gridDim.x;
                const int rj = samples[ri];
                const float diff  = (r0 - r1) * TEMP_INV;
                const float p     = 1.0f / (1.0f + expf(-diff));
                const float label = (y[ri] != y[rj]) ? 1.0f : 0.0f;
                shloss[r] = -logf(p + EPS) * label
                            - logf(1.0f - p + EPS) * (1.0f - label);
            }
        }
    }
    __syncthreads();

    // block total + grid finalize (warp 0)
    if (w == 0) {
        float loss = (lane < niter) ? shloss[lane] : 0.0f;
        #pragma unroll
        for (int o = 16; o > 0; o >>= 1)
            loss += __shfl_xor_sync(0xFFFFFFFFu, loss, o);

        if (lane == 0) {
            atomicAdd(&g_accum, loss);             // relaxed, performed at L2

            unsigned int t;
            asm volatile("atom.add.acq_rel.gpu.global.u32 %0, [%1], 1;"
                         : "=r"(t) : "l"(&g_ticket) : "memory");

            if (t % gridDim.x == gridDim.x - 1) {  // last block to arrive
                const float total = atomicAdd(&g_accum, 0.0f);
                out[0] = total * invB;
                atomicExch(&g_accum, 0.0f);        // reset for next replay
            }
        }
    }
}

extern "C" void kernel_launch(void* const* d_in, const int* in_sizes, int n_in,
                              void* d_out, int out_size)
{
    const float* x       = (const float*)d_in[0];
    const int*   y       = (const int*)d_in[1];
    const int*   samples = (const int*)d_in[2];
    float* out = (float*)d_out;

    const int B = in_sizes[1];                 // 16384
    const int D = in_sizes[0] / in_sizes[1];   // 2048

    int blocks = GRID_BLOCKS;                  // 1184 persistent blocks
    if (blocks > B) blocks = B;

    fused_loss_kernel<<<blocks, 256>>>(x, y, samples, out, B, D, 1.0f / (float)B);
}